// round 3
// baseline (speedup 1.0000x reference)
#include <cuda_runtime.h>

// RoiDeform: output (B=2, k*k=16, cs=384, cs=384, C=3) fp32.
// All cs output rows within a bin are identical -> compute one sampled row
// per bin into smem, then broadcast-write it with coalesced float4 stores.

#define BATCH 2
#define IMG_H 1600
#define IMG_W 1600
#define CH 3
#define KK 4
#define CS 384
#define PAD 32                 // (1600 - 384*4)/2
#define ROW_FLOATS (CS * CH)   // 1152
#define ROW_F4 (ROW_FLOATS/4)  // 288
#define ROWS_PER_BLOCK 24      // 384/24 = 16 chunks per bin
#define THREADS 384

__global__ __launch_bounds__(THREADS)
void roi_deform_kernel(const float* __restrict__ img,
                       const float* __restrict__ delta_p,
                       float* __restrict__ out)
{
    __shared__ float row[ROW_FLOATS];
    __shared__ float4 row4_alias[ROW_F4];  // same bytes via union-style reuse
    // (use row directly; alias array only to guarantee 16B alignment)
    (void)row4_alias;

    const int b    = blockIdx.z;          // 0..1
    const int bin  = blockIdx.y;          // 0..15
    const int bi   = bin >> 2;            // i
    const int bj   = bin & 3;             // j
    const int tid  = threadIdx.x;         // 0..383

    // per-bin offsets
    const float dp0 = __ldg(&delta_p[(((b * KK + bi) * KK) + bj) * 2 + 0]);
    const float dp1 = __ldg(&delta_p[(((b * KK + bi) * KK) + bj) * 2 + 1]);

    // ---- Phase 1: each thread computes one bilinear sample (3 channels) ----
    {
        const int s = tid;  // 0..383
        const float r = (float)(PAD + bi * CS + s) + dp0;
        const float c = (float)(PAD + bj * CS + s) + dp1;
        const float r0f = floorf(r);
        const float c0f = floorf(c);
        const float rf = r - r0f;
        const float cf = c - c0f;
        const int r0 = (int)r0f;
        const int c0 = (int)c0f;

        float a0 = 0.f, a1 = 0.f, a2 = 0.f;
        #pragma unroll
        for (int dr = 0; dr < 2; ++dr) {
            const int   ri = r0 + dr;
            const float wr = dr ? rf : (1.0f - rf);
            if (ri >= 0 && ri < IMG_H) {
                #pragma unroll
                for (int dc = 0; dc < 2; ++dc) {
                    const int   ci = c0 + dc;
                    const float wc = dc ? cf : (1.0f - cf);
                    if (ci >= 0 && ci < IMG_W) {
                        const float w = wr * wc;
                        const float* p = img + ((size_t)((size_t)b * IMG_H + ri) * IMG_W + ci) * CH;
                        a0 += w * __ldg(p + 0);
                        a1 += w * __ldg(p + 1);
                        a2 += w * __ldg(p + 2);
                    }
                }
            }
        }
        row[s * 3 + 0] = a0;
        row[s * 3 + 1] = a1;
        row[s * 3 + 2] = a2;
    }
    __syncthreads();

    // ---- Phase 2: broadcast-write ROWS_PER_BLOCK identical rows, float4 ----
    const float4* sm4 = reinterpret_cast<const float4*>(row);
    const size_t row_base = ((size_t)(b * (KK * KK) + bin) * CS
                             + (size_t)blockIdx.x * ROWS_PER_BLOCK);
    float4* out4 = reinterpret_cast<float4*>(out) + row_base * ROW_F4;

    const int total = ROWS_PER_BLOCK * ROW_F4;  // 6912
    for (int idx = tid; idx < total; idx += THREADS) {
        const int rr = idx / ROW_F4;
        const int q  = idx - rr * ROW_F4;
        out4[(size_t)rr * ROW_F4 + q] = sm4[q];
    }
}

extern "C" void kernel_launch(void* const* d_in, const int* in_sizes, int n_in,
                              void* d_out, int out_size)
{
    const float* img = (const float*)d_in[0];
    const float* dp  = (const float*)d_in[1];
    float* out = (float*)d_out;
    (void)in_sizes; (void)n_in; (void)out_size;

    dim3 grid(CS / ROWS_PER_BLOCK, KK * KK, BATCH);  // (16, 16, 2)
    roi_deform_kernel<<<grid, THREADS>>>(img, dp, out);
}

// round 4
// speedup vs baseline: 1.0152x; 1.0152x over previous
#include <cuda_runtime.h>
#include <cstdint>

// RoiDeform: output (B=2, k*k=16, cs=384, cs=384, C=3) fp32.
// All 384 output rows within a bin are identical. Compute one sampled row,
// replicate it 6x in smem, then TMA-bulk-store 4 x 27648B contiguous chunks
// per block (24 rows), bypassing the per-thread STG/L1 path entirely.

#define BATCH 2
#define IMG_H 1600
#define IMG_W 1600
#define CH 3
#define KK 4
#define CS 384
#define PAD 32                     // (1600 - 384*4)/2
#define ROW_FLOATS (CS * CH)       // 1152
#define ROW_BYTES (ROW_FLOATS * 4) // 4608
#define R_COPIES 6                 // rows replicated in smem
#define ROWS_PER_BLOCK 24          // 384/24 = 16 chunks per bin
#define N_BULK (ROWS_PER_BLOCK / R_COPIES)   // 4 bulk copies per block
#define CHUNK_BYTES (R_COPIES * ROW_BYTES)   // 27648
#define THREADS 384

__device__ __forceinline__ uint32_t smem_u32(const void* p) {
    uint32_t a;
    asm("{ .reg .u64 t; cvta.to.shared.u64 t, %1; cvt.u32.u64 %0, t; }"
        : "=r"(a) : "l"(p));
    return a;
}

__global__ __launch_bounds__(THREADS)
void roi_deform_kernel(const float* __restrict__ img,
                       const float* __restrict__ delta_p,
                       float* __restrict__ out)
{
    __shared__ __align__(128) float buf[R_COPIES * ROW_FLOATS];  // 27648 B

    const int b    = blockIdx.z;          // 0..1
    const int bin  = blockIdx.y;          // 0..15
    const int bi   = bin >> 2;            // i
    const int bj   = bin & 3;             // j
    const int tid  = threadIdx.x;         // 0..383

    const float dp0 = __ldg(&delta_p[(((b * KK + bi) * KK) + bj) * 2 + 0]);
    const float dp1 = __ldg(&delta_p[(((b * KK + bi) * KK) + bj) * 2 + 1]);

    // ---- Phase 1: each thread computes one bilinear sample (3 channels),
    //      stores it into all R_COPIES smem row copies ----
    {
        const int s = tid;  // 0..383
        const float r = (float)(PAD + bi * CS + s) + dp0;
        const float c = (float)(PAD + bj * CS + s) + dp1;
        const float r0f = floorf(r);
        const float c0f = floorf(c);
        const float rf = r - r0f;
        const float cf = c - c0f;
        const int r0 = (int)r0f;
        const int c0 = (int)c0f;

        float a0 = 0.f, a1 = 0.f, a2 = 0.f;
        #pragma unroll
        for (int dr = 0; dr < 2; ++dr) {
            const int   ri = r0 + dr;
            const float wr = dr ? rf : (1.0f - rf);
            if (ri >= 0 && ri < IMG_H) {
                #pragma unroll
                for (int dc = 0; dc < 2; ++dc) {
                    const int   ci = c0 + dc;
                    const float wc = dc ? cf : (1.0f - cf);
                    if (ci >= 0 && ci < IMG_W) {
                        const float w = wr * wc;
                        const float* p = img + ((size_t)((size_t)b * IMG_H + ri) * IMG_W + ci) * CH;
                        a0 += w * __ldg(p + 0);
                        a1 += w * __ldg(p + 1);
                        a2 += w * __ldg(p + 2);
                    }
                }
            }
        }
        #pragma unroll
        for (int cp = 0; cp < R_COPIES; ++cp) {
            float* dst = buf + cp * ROW_FLOATS + s * 3;
            dst[0] = a0;
            dst[1] = a1;
            dst[2] = a2;
        }
    }
    __syncthreads();

    // ---- Phase 2: one thread issues N_BULK TMA bulk stores (27648B each) ----
    if (tid == 0) {
        // Order the generic-proxy STS writes before async-proxy reads.
        asm volatile("fence.proxy.async.shared::cta;" ::: "memory");

        const uint32_t src = smem_u32(buf);
        const size_t row_base = ((size_t)(b * (KK * KK) + bin) * CS
                                 + (size_t)blockIdx.x * ROWS_PER_BLOCK);
        char* gdst = (char*)out + row_base * ROW_BYTES;

        #pragma unroll
        for (int g = 0; g < N_BULK; ++g) {
            asm volatile(
                "cp.async.bulk.global.shared::cta.bulk_group [%0], [%1], %2;"
                :: "l"(gdst + (size_t)g * CHUNK_BYTES), "r"(src), "n"(CHUNK_BYTES)
                : "memory");
        }
        asm volatile("cp.async.bulk.commit_group;" ::: "memory");
        asm volatile("cp.async.bulk.wait_group 0;" ::: "memory");
    }
}

extern "C" void kernel_launch(void* const* d_in, const int* in_sizes, int n_in,
                              void* d_out, int out_size)
{
    const float* img = (const float*)d_in[0];
    const float* dp  = (const float*)d_in[1];
    float* out = (float*)d_out;
    (void)in_sizes; (void)n_in; (void)out_size;

    dim3 grid(CS / ROWS_PER_BLOCK, KK * KK, BATCH);  // (16, 16, 2)
    roi_deform_kernel<<<grid, THREADS>>>(img, dp, out);
}

// round 5
// speedup vs baseline: 1.1404x; 1.1234x over previous
#include <cuda_runtime.h>
#include <cstdint>

// RoiDeform: output (B=2, k*k=16, cs=384, cs=384, C=3) fp32.
// All 384 output rows within a bin are identical.
// Kernel A: compute the 32 unique sampled rows once into device scratch.
// Kernel B: many small blocks broadcast rows from L2-resident scratch with
//           coalesced STG.128 — short dependence chains, deep overlap.

#define BATCH 2
#define IMG_H 1600
#define IMG_W 1600
#define CH 3
#define KK 4
#define CS 384
#define PAD 32                     // (1600 - 384*4)/2
#define ROW_FLOATS (CS * CH)       // 1152
#define ROW_F4 (ROW_FLOATS / 4)    // 288
#define NROWS (BATCH * KK * KK)    // 32 unique rows
#define RPB 6                      // rows written per block (kernel B)
#define CHUNKS (CS / RPB)          // 64
#define THREADS_B ROW_F4           // 288 (9 warps)

__device__ __align__(16) float g_row[NROWS * ROW_FLOATS];  // 147 KB scratch

// ---------------- Kernel A: compute 32 unique rows ----------------
__global__ __launch_bounds__(CS)
void row_compute_kernel(const float* __restrict__ img,
                        const float* __restrict__ delta_p)
{
    const int rowid = blockIdx.x;       // 0..31  = b*16 + bin
    const int b   = rowid >> 4;
    const int bin = rowid & 15;
    const int bi  = bin >> 2;
    const int bj  = bin & 3;
    const int s   = threadIdx.x;        // 0..383

    const float dp0 = __ldg(&delta_p[rowid * 2 + 0]);
    const float dp1 = __ldg(&delta_p[rowid * 2 + 1]);

    const float r = (float)(PAD + bi * CS + s) + dp0;
    const float c = (float)(PAD + bj * CS + s) + dp1;
    const float r0f = floorf(r);
    const float c0f = floorf(c);
    const float rf = r - r0f;
    const float cf = c - c0f;
    const int r0 = (int)r0f;
    const int c0 = (int)c0f;

    float a0 = 0.f, a1 = 0.f, a2 = 0.f;
    #pragma unroll
    for (int dr = 0; dr < 2; ++dr) {
        const int   ri = r0 + dr;
        const float wr = dr ? rf : (1.0f - rf);
        if (ri >= 0 && ri < IMG_H) {
            #pragma unroll
            for (int dc = 0; dc < 2; ++dc) {
                const int   ci = c0 + dc;
                const float wc = dc ? cf : (1.0f - cf);
                if (ci >= 0 && ci < IMG_W) {
                    const float w = wr * wc;
                    const float* p = img +
                        ((size_t)((size_t)b * IMG_H + ri) * IMG_W + ci) * CH;
                    a0 += w * __ldg(p + 0);
                    a1 += w * __ldg(p + 1);
                    a2 += w * __ldg(p + 2);
                }
            }
        }
    }
    float* dst = g_row + (size_t)rowid * ROW_FLOATS + s * 3;
    dst[0] = a0;
    dst[1] = a1;
    dst[2] = a2;
}

// ---------------- Kernel B: broadcast rows to output ----------------
__global__ __launch_bounds__(THREADS_B)
void row_broadcast_kernel(float* __restrict__ out)
{
    const int chunk = blockIdx.x;                   // 0..63
    const int bin   = blockIdx.y;                   // 0..15
    const int b     = blockIdx.z;                   // 0..1
    const int rowid = b * (KK * KK) + bin;
    const int q     = threadIdx.x;                  // 0..287

    const float4 v = __ldg(reinterpret_cast<const float4*>(
                               g_row + (size_t)rowid * ROW_FLOATS) + q);

    float4* out4 = reinterpret_cast<float4*>(out) +
                   ((size_t)rowid * CS + (size_t)chunk * RPB) * ROW_F4 + q;
    #pragma unroll
    for (int r = 0; r < RPB; ++r) {
        out4[(size_t)r * ROW_F4] = v;
    }
}

extern "C" void kernel_launch(void* const* d_in, const int* in_sizes, int n_in,
                              void* d_out, int out_size)
{
    const float* img = (const float*)d_in[0];
    const float* dp  = (const float*)d_in[1];
    float* out = (float*)d_out;
    (void)in_sizes; (void)n_in; (void)out_size;

    row_compute_kernel<<<NROWS, CS>>>(img, dp);
    dim3 gridB(CHUNKS, KK * KK, BATCH);             // (64, 16, 2) = 2048
    row_broadcast_kernel<<<gridB, THREADS_B>>>(out);
}

// round 6
// speedup vs baseline: 1.1577x; 1.0151x over previous
#include <cuda_runtime.h>
#include <cstdint>

// RoiDeform: output (B=2, k*k=16, cs=384, cs=384, C=3) fp32.
// All 384 output rows within a bin are identical.
// Kernel A: compute the 32 unique sampled rows once into device scratch.
// Kernel B: single-wave broadcast (1024 blocks = 7/SM), 12 rows/block,
//           launched with PDL so its setup overlaps kernel A.

#define BATCH 2
#define IMG_H 1600
#define IMG_W 1600
#define CH 3
#define KK 4
#define CS 384
#define PAD 32                     // (1600 - 384*4)/2
#define ROW_FLOATS (CS * CH)       // 1152
#define ROW_F4 (ROW_FLOATS / 4)    // 288
#define NROWS (BATCH * KK * KK)    // 32 unique rows
#define RPB 12                     // rows written per block (kernel B)
#define CHUNKS (CS / RPB)          // 32
#define THREADS_B ROW_F4           // 288 (9 warps)

__device__ __align__(16) float g_row[NROWS * ROW_FLOATS];  // 147 KB scratch

// ---------------- Kernel A: compute 32 unique rows ----------------
__global__ __launch_bounds__(CS)
void row_compute_kernel(const float* __restrict__ img,
                        const float* __restrict__ delta_p)
{
    const int rowid = blockIdx.x;       // 0..31  = b*16 + bin
    const int b   = rowid >> 4;
    const int bin = rowid & 15;
    const int bi  = bin >> 2;
    const int bj  = bin & 3;
    const int s   = threadIdx.x;        // 0..383

    const float dp0 = __ldg(&delta_p[rowid * 2 + 0]);
    const float dp1 = __ldg(&delta_p[rowid * 2 + 1]);

    const float r = (float)(PAD + bi * CS + s) + dp0;
    const float c = (float)(PAD + bj * CS + s) + dp1;
    const float r0f = floorf(r);
    const float c0f = floorf(c);
    const float rf = r - r0f;
    const float cf = c - c0f;
    const int r0 = (int)r0f;
    const int c0 = (int)c0f;

    float a0 = 0.f, a1 = 0.f, a2 = 0.f;
    #pragma unroll
    for (int dr = 0; dr < 2; ++dr) {
        const int   ri = r0 + dr;
        const float wr = dr ? rf : (1.0f - rf);
        if (ri >= 0 && ri < IMG_H) {
            #pragma unroll
            for (int dc = 0; dc < 2; ++dc) {
                const int   ci = c0 + dc;
                const float wc = dc ? cf : (1.0f - cf);
                if (ci >= 0 && ci < IMG_W) {
                    const float w = wr * wc;
                    const float* p = img +
                        ((size_t)((size_t)b * IMG_H + ri) * IMG_W + ci) * CH;
                    a0 += w * __ldg(p + 0);
                    a1 += w * __ldg(p + 1);
                    a2 += w * __ldg(p + 2);
                }
            }
        }
    }
    float* dst = g_row + (size_t)rowid * ROW_FLOATS + s * 3;
    dst[0] = a0;
    dst[1] = a1;
    dst[2] = a2;
}

// ---------------- Kernel B: broadcast rows to output ----------------
__global__ __launch_bounds__(THREADS_B)
void row_broadcast_kernel(float* __restrict__ out)
{
    const int chunk = blockIdx.x;                   // 0..31
    const int bin   = blockIdx.y;                   // 0..15
    const int b     = blockIdx.z;                   // 0..1
    const int rowid = b * (KK * KK) + bin;
    const int q     = threadIdx.x;                  // 0..287

    const float4* src = reinterpret_cast<const float4*>(
                            g_row + (size_t)rowid * ROW_FLOATS) + q;
    float4* out4 = reinterpret_cast<float4*>(out) +
                   ((size_t)rowid * CS + (size_t)chunk * RPB) * ROW_F4 + q;

    // PDL: all setup above overlaps kernel A; block here until A's writes
    // to g_row are visible.
    cudaGridDependencySynchronize();

    const float4 v = __ldg(src);
    #pragma unroll
    for (int r = 0; r < RPB; ++r) {
        out4[(size_t)r * ROW_F4] = v;
    }
}

extern "C" void kernel_launch(void* const* d_in, const int* in_sizes, int n_in,
                              void* d_out, int out_size)
{
    const float* img = (const float*)d_in[0];
    const float* dp  = (const float*)d_in[1];
    float* out = (float*)d_out;
    (void)in_sizes; (void)n_in; (void)out_size;

    row_compute_kernel<<<NROWS, CS>>>(img, dp);

    // Kernel B with programmatic dependent launch: overlap its launch/setup
    // with kernel A; correctness via cudaGridDependencySynchronize() in B.
    cudaLaunchConfig_t cfg = {};
    cfg.gridDim  = dim3(CHUNKS, KK * KK, BATCH);    // (32, 16, 2) = 1024
    cfg.blockDim = dim3(THREADS_B, 1, 1);
    cfg.dynamicSmemBytes = 0;
    cfg.stream = 0;
    cudaLaunchAttribute attr[1];
    attr[0].id = cudaLaunchAttributeProgrammaticStreamSerialization;
    attr[0].val.programmaticStreamSerializationAllowed = 1;
    cfg.attrs = attr;
    cfg.numAttrs = 1;
    cudaLaunchKernelEx(&cfg, row_broadcast_kernel, out);
}